// round 1
// baseline (speedup 1.0000x reference)
#include <cuda_runtime.h>
#include <cstdint>
#include <cstddef>

#define NUSERS 100000
#define NITEMS 100000
#define DIN 128
#define DOUT 128
#define NSUP 5
#define NEDGE 500000

// Scratch: cumulative weights and dense GEMM results.
// g_T[side][s][row*128+col] : side 0 = user_inputs @ Wc[s], side 1 = item_inputs @ Wc[s]
__device__ float g_Wc[NSUP][DIN * DOUT];            // 320 KB
__device__ float g_T[2][NSUP][(size_t)NUSERS * 128]; // 512 MB

// ---------------------------------------------------------------------------
// Cumulative weight: Wc[s] = sum_{j<=s} weight[:,:,j]
// weight layout: [din][dout][s]  -> idx = din*640 + dout*5 + s
// ---------------------------------------------------------------------------
__global__ void wcum_kernel(const float* __restrict__ w) {
    int din = blockIdx.x;
    int dout = threadIdx.x;
    const float* p = w + ((size_t)din * DOUT + dout) * NSUP;
    float acc = 0.f;
#pragma unroll
    for (int s = 0; s < NSUP; s++) {
        acc += p[s];
        g_Wc[s][din * DOUT + dout] = acc;
    }
}

// ---------------------------------------------------------------------------
// Dense GEMM: g_T[side][s] = X @ Wc[s],  X is [100000,128], Wc [128,128]
// grid: (ceil(M/64), NSUP, 2), block 256.
// BM=64, BN=128, BK=8, per-thread micro-tile 8x4.
// ---------------------------------------------------------------------------
__global__ __launch_bounds__(256) void gemm_kernel(const float* __restrict__ U,
                                                   const float* __restrict__ In) {
    const int side = blockIdx.z;
    const int s = blockIdx.y;
    const float* __restrict__ X = (side == 0) ? U : In;
    const int M = NUSERS;
    const int row0 = blockIdx.x * 64;

    __shared__ float As[8][64];
    __shared__ float Bs[8][128];

    const int t = threadIdx.x;
    const int tn = (t & 31) * 4;  // output col offset within 128
    const int tm = (t >> 5) * 8;  // output row offset within 64

    // A-tile loader mapping: each thread loads 2 consecutive floats (64x8 tile)
    const int rA = (t * 2) >> 3;  // 0..63
    const int cA = (t * 2) & 7;   // 0,2,4,6
    const bool okA = (row0 + rA) < M;
    const float* gA = X + (size_t)(row0 + rA) * 128 + cA;

    // B-tile loader mapping: each thread loads one float4 (8x128 tile)
    const int kB = t >> 5;        // 0..7
    const int nB = (t & 31) * 4;  // 0..124
    const float* gW = g_Wc[s];

    float acc[8][4];
#pragma unroll
    for (int i = 0; i < 8; i++)
#pragma unroll
        for (int j = 0; j < 4; j++) acc[i][j] = 0.f;

    for (int k0 = 0; k0 < 128; k0 += 8) {
        float2 av = okA ? *(const float2*)(gA + k0) : make_float2(0.f, 0.f);
        float4 bv = *(const float4*)(gW + (size_t)(k0 + kB) * 128 + nB);
        __syncthreads();  // previous iteration's consumers done
        As[cA][rA] = av.x;
        As[cA + 1][rA] = av.y;
        *(float4*)&Bs[kB][nB] = bv;
        __syncthreads();
#pragma unroll
        for (int kk = 0; kk < 8; kk++) {
            float4 b = *(const float4*)&Bs[kk][tn];
            float4 a0 = *(const float4*)&As[kk][tm];
            float4 a1 = *(const float4*)&As[kk][tm + 4];
            float a[8] = {a0.x, a0.y, a0.z, a0.w, a1.x, a1.y, a1.z, a1.w};
            float bb[4] = {b.x, b.y, b.z, b.w};
#pragma unroll
            for (int i = 0; i < 8; i++)
#pragma unroll
                for (int j = 0; j < 4; j++) acc[i][j] += a[i] * bb[j];
        }
    }

    float* T = g_T[side][s];
#pragma unroll
    for (int i = 0; i < 8; i++) {
        int row = row0 + tm + i;
        if (row < M)
            *(float4*)&T[(size_t)row * 128 + tn] =
                make_float4(acc[i][0], acc[i][1], acc[i][2], acc[i][3]);
    }
}

// ---------------------------------------------------------------------------
// Gather-SpMM: out[rows[e], :] += vals[e] * g_T[tSide][s][cols[e], :]
// One warp per edge; each lane handles 4 floats via vector red.
// ---------------------------------------------------------------------------
__global__ __launch_bounds__(256) void spmm_kernel(const int* __restrict__ rows,
                                                   const int* __restrict__ cols,
                                                   const float* __restrict__ vals,
                                                   int tSide, int s,
                                                   float* __restrict__ out, int nE) {
    int e = (int)((blockIdx.x * 256u + threadIdx.x) >> 5);
    if (e >= nE) return;
    int lane = threadIdx.x & 31;
    int r = __ldg(&rows[e]);
    int c = __ldg(&cols[e]);
    float v = __ldg(&vals[e]);
    const float4* src = (const float4*)(g_T[tSide][s] + (size_t)c * 128);
    float4 x = src[lane];
    float* dst = out + (size_t)r * 128 + lane * 4;
    float4 y = make_float4(v * x.x, v * x.y, v * x.z, v * x.w);
    asm volatile("red.global.add.v4.f32 [%0], {%1,%2,%3,%4};"
                 :: "l"(dst), "f"(y.x), "f"(y.y), "f"(y.z), "f"(y.w)
                 : "memory");
}

// ---------------------------------------------------------------------------
// ReLU over the whole output (float4 granularity).
// ---------------------------------------------------------------------------
__global__ void relu_kernel(float* __restrict__ out, int n4) {
    int i = blockIdx.x * 256 + threadIdx.x;
    if (i < n4) {
        float4 v = ((float4*)out)[i];
        v.x = fmaxf(v.x, 0.f);
        v.y = fmaxf(v.y, 0.f);
        v.z = fmaxf(v.z, 0.f);
        v.w = fmaxf(v.w, 0.f);
        ((float4*)out)[i] = v;
    }
}

// ---------------------------------------------------------------------------
// kernel_launch
// inputs: 0 user_inputs [NU,128] f32, 1 item_inputs [NI,128] f32,
//         2 weight [128,128,5] f32,
//         3 u_rows [5,500000] i32, 4 u_cols, 5 u_vals f32,
//         6 i_rows, 7 i_cols, 8 i_vals
// output: [relu(user_hidden) (NU*128) ; relu(item_hidden) (NI*128)] f32
// ---------------------------------------------------------------------------
extern "C" void kernel_launch(void* const* d_in, const int* in_sizes, int n_in,
                              void* d_out, int out_size) {
    const float* U = (const float*)d_in[0];
    const float* It = (const float*)d_in[1];
    const float* W = (const float*)d_in[2];
    const int* u_rows = (const int*)d_in[3];
    const int* u_cols = (const int*)d_in[4];
    const float* u_vals = (const float*)d_in[5];
    const int* i_rows = (const int*)d_in[6];
    const int* i_cols = (const int*)d_in[7];
    const float* i_vals = (const float*)d_in[8];
    float* out = (float*)d_out;

    cudaMemsetAsync(d_out, 0, (size_t)out_size * sizeof(float), 0);

    wcum_kernel<<<DIN, DOUT>>>(W);

    dim3 g((NUSERS + 63) / 64, NSUP, 2);
    gemm_kernel<<<g, 256>>>(U, It);

    const int spmmBlocks = (NEDGE * 32 + 255) / 256;  // warp per edge
    // user_hidden gathers from item T (side 1); keep out_user hot in L2 across supports
    for (int s = 0; s < NSUP; s++)
        spmm_kernel<<<spmmBlocks, 256>>>(u_rows + (size_t)s * NEDGE,
                                         u_cols + (size_t)s * NEDGE,
                                         u_vals + (size_t)s * NEDGE,
                                         1, s, out, NEDGE);
    // item_hidden gathers from user T (side 0)
    for (int s = 0; s < NSUP; s++)
        spmm_kernel<<<spmmBlocks, 256>>>(i_rows + (size_t)s * NEDGE,
                                         i_cols + (size_t)s * NEDGE,
                                         i_vals + (size_t)s * NEDGE,
                                         0, s, out + (size_t)NUSERS * 128, NEDGE);

    const int n4 = (NUSERS + NITEMS) * 128 / 4;
    relu_kernel<<<(n4 + 255) / 256, 256>>>(out, n4);
}

// round 2
// speedup vs baseline: 1.0929x; 1.0929x over previous
#include <cuda_runtime.h>
#include <cstdint>
#include <cstddef>

#define NUSERS 100000
#define NITEMS 100000
#define DIN 128
#define DOUT 128
#define NSUP 5
#define NEDGE 500000
#define MTILES ((NUSERS + 127) / 128)

// Scratch: cumulative weights (tf32-rounded) and dense GEMM results.
__device__ float g_Wc[NSUP][DIN * DOUT];             // 320 KB
__device__ float g_T[2][NSUP][(size_t)NUSERS * 128]; // 512 MB

// ---------------------------------------------------------------------------
// Cumulative weight, rounded to tf32 (B operand of the tensor GEMM).
// weight layout [din][dout][s]
// ---------------------------------------------------------------------------
__global__ void wcum_kernel(const float* __restrict__ w) {
    int din = blockIdx.x;
    int dout = threadIdx.x;
    const float* p = w + ((size_t)din * DOUT + dout) * NSUP;
    float acc = 0.f;
#pragma unroll
    for (int s = 0; s < NSUP; s++) {
        acc += p[s];
        uint32_t r;
        asm("cvt.rna.tf32.f32 %0, %1;" : "=r"(r) : "f"(acc));
        g_Wc[s][din * DOUT + dout] = __uint_as_float(r);
    }
}

// ---------------------------------------------------------------------------
// Tensor-core GEMM (tf32 mma.sync m16n8k8):
//   g_T[side][s] = X @ Wc[s],  X [100000,128], Wc [128,128]
// Block 128 thr = 4 warps (2m x 2n), block tile 128x128, warp tile 64x64.
// K chunked at 16, cp.async double-buffered.
// smem pads: A row stride 20 words, B row stride 136 words (conflict-free frags).
// ---------------------------------------------------------------------------
#define KC 16
#define ASTR 20
#define BSTR 136

__device__ __forceinline__ void cp16(float* sdst, const float* gsrc) {
    unsigned u = (unsigned)__cvta_generic_to_shared(sdst);
    asm volatile("cp.async.cg.shared.global [%0], [%1], 16;" :: "r"(u), "l"(gsrc));
}

#define MMA_TF32(c, a, b)                                                    \
    asm volatile(                                                            \
        "mma.sync.aligned.m16n8k8.row.col.f32.tf32.tf32.f32 "               \
        "{%0,%1,%2,%3}, {%4,%5,%6,%7}, {%8,%9}, {%0,%1,%2,%3};"             \
        : "+f"(c[0]), "+f"(c[1]), "+f"(c[2]), "+f"(c[3])                     \
        : "r"(a[0]), "r"(a[1]), "r"(a[2]), "r"(a[3]), "r"(b[0]), "r"(b[1]))

__global__ __launch_bounds__(128) void gemm_kernel(const float* __restrict__ U,
                                                   const float* __restrict__ In) {
    const int s = blockIdx.x;
    const int side = blockIdx.z;
    const float* __restrict__ X = (side == 0) ? U : In;
    const int row0 = blockIdx.y * 128;

    __shared__ float sA[2][128 * ASTR];  // 18.75 KB
    __shared__ float sB[2][KC * BSTR];   // 17.0 KB

    const int t = threadIdx.x;
    const int wid = t >> 5;
    const int lane = t & 31;
    const int gid = lane >> 2;   // 0..7
    const int tig = lane & 3;    // 0..3
    const int wm = (wid & 1) * 64;
    const int wn = (wid >> 1) * 64;

    const float* gW = g_Wc[s];

    float c[4][8][4];
#pragma unroll
    for (int mt = 0; mt < 4; mt++)
#pragma unroll
        for (int nt = 0; nt < 8; nt++)
#pragma unroll
            for (int i = 0; i < 4; i++) c[mt][nt][i] = 0.f;

    // ---- async copy of one K-chunk into buffer b ----
    auto copy_chunk = [&](int kc, int b) {
        // A: 128 rows x 16 floats = 512 quads, 4 per thread
#pragma unroll
        for (int i = 0; i < 4; i++) {
            int q = t + 128 * i;
            int row = q >> 2, c4 = (q & 3) * 4;
            int gr = row0 + row;
            if (gr > NUSERS - 1) gr = NUSERS - 1;  // clamp; stores are guarded
            cp16(&sA[b][row * ASTR + c4], X + (size_t)gr * 128 + kc * KC + c4);
        }
        // B: 16 k-rows x 128 floats = 512 quads
#pragma unroll
        for (int i = 0; i < 4; i++) {
            int q = t + 128 * i;
            int kr = q >> 5, c4 = (q & 31) * 4;
            cp16(&sB[b][kr * BSTR + c4], gW + (size_t)(kc * KC + kr) * 128 + c4);
        }
        asm volatile("cp.async.commit_group;");
    };

    copy_chunk(0, 0);
    int buf = 0;

    for (int kc = 0; kc < 128 / KC; kc++) {
        if (kc + 1 < 128 / KC) {
            copy_chunk(kc + 1, buf ^ 1);
            asm volatile("cp.async.wait_group 1;");
        } else {
            asm volatile("cp.async.wait_group 0;");
        }
        __syncthreads();

        const float* A = sA[buf];
        const float* B = sB[buf];
#pragma unroll
        for (int ks = 0; ks < KC / 8; ks++) {
            uint32_t a[4][4], b[8][2];
#pragma unroll
            for (int mt = 0; mt < 4; mt++) {
                int r = wm + mt * 16 + gid;
                int kk = ks * 8 + tig;
                float f0 = A[r * ASTR + kk];
                float f1 = A[(r + 8) * ASTR + kk];
                float f2 = A[r * ASTR + kk + 4];
                float f3 = A[(r + 8) * ASTR + kk + 4];
                asm("cvt.rna.tf32.f32 %0, %1;" : "=r"(a[mt][0]) : "f"(f0));
                asm("cvt.rna.tf32.f32 %0, %1;" : "=r"(a[mt][1]) : "f"(f1));
                asm("cvt.rna.tf32.f32 %0, %1;" : "=r"(a[mt][2]) : "f"(f2));
                asm("cvt.rna.tf32.f32 %0, %1;" : "=r"(a[mt][3]) : "f"(f3));
            }
#pragma unroll
            for (int nt = 0; nt < 8; nt++) {
                int col = wn + nt * 8 + gid;
                b[nt][0] = __float_as_uint(B[(ks * 8 + tig) * BSTR + col]);
                b[nt][1] = __float_as_uint(B[(ks * 8 + tig + 4) * BSTR + col]);
            }
#pragma unroll
            for (int mt = 0; mt < 4; mt++)
#pragma unroll
                for (int nt = 0; nt < 8; nt++) MMA_TF32(c[mt][nt], a[mt], b[nt]);
        }
        buf ^= 1;
        __syncthreads();  // all warps done with old buf before its next prefetch
    }

    float* T = g_T[side][s];
#pragma unroll
    for (int mt = 0; mt < 4; mt++) {
        int r0 = row0 + wm + mt * 16 + gid;
        int r1 = r0 + 8;
#pragma unroll
        for (int nt = 0; nt < 8; nt++) {
            int cg = wn + nt * 8 + tig * 2;
            if (r0 < NUSERS)
                *(float2*)&T[(size_t)r0 * 128 + cg] = make_float2(c[mt][nt][0], c[mt][nt][1]);
            if (r1 < NUSERS)
                *(float2*)&T[(size_t)r1 * 128 + cg] = make_float2(c[mt][nt][2], c[mt][nt][3]);
        }
    }
}

// ---------------------------------------------------------------------------
// Gather-SpMM: out[rows[e], :] += vals[e] * g_T[tSide][s][cols[e], :]
// One warp per edge; vector red per lane. (REDG-bound; CSR restructure next.)
// ---------------------------------------------------------------------------
__global__ __launch_bounds__(256) void spmm_kernel(const int* __restrict__ rows,
                                                   const int* __restrict__ cols,
                                                   const float* __restrict__ vals,
                                                   int tSide, int s,
                                                   float* __restrict__ out, int nE) {
    int e = (int)((blockIdx.x * 256u + threadIdx.x) >> 5);
    if (e >= nE) return;
    int lane = threadIdx.x & 31;
    int r = __ldg(&rows[e]);
    int c = __ldg(&cols[e]);
    float v = __ldg(&vals[e]);
    const float4* src = (const float4*)(g_T[tSide][s] + (size_t)c * 128);
    float4 x = src[lane];
    float* dst = out + (size_t)r * 128 + lane * 4;
    float4 y = make_float4(v * x.x, v * x.y, v * x.z, v * x.w);
    asm volatile("red.global.add.v4.f32 [%0], {%1,%2,%3,%4};"
                 :: "l"(dst), "f"(y.x), "f"(y.y), "f"(y.z), "f"(y.w)
                 : "memory");
}

// ---------------------------------------------------------------------------
// ReLU over the whole output.
// ---------------------------------------------------------------------------
__global__ void relu_kernel(float* __restrict__ out, int n4) {
    int i = blockIdx.x * 256 + threadIdx.x;
    if (i < n4) {
        float4 v = ((float4*)out)[i];
        v.x = fmaxf(v.x, 0.f);
        v.y = fmaxf(v.y, 0.f);
        v.z = fmaxf(v.z, 0.f);
        v.w = fmaxf(v.w, 0.f);
        ((float4*)out)[i] = v;
    }
}

extern "C" void kernel_launch(void* const* d_in, const int* in_sizes, int n_in,
                              void* d_out, int out_size) {
    const float* U = (const float*)d_in[0];
    const float* It = (const float*)d_in[1];
    const float* W = (const float*)d_in[2];
    const int* u_rows = (const int*)d_in[3];
    const int* u_cols = (const int*)d_in[4];
    const float* u_vals = (const float*)d_in[5];
    const int* i_rows = (const int*)d_in[6];
    const int* i_cols = (const int*)d_in[7];
    const float* i_vals = (const float*)d_in[8];
    float* out = (float*)d_out;

    cudaMemsetAsync(d_out, 0, (size_t)out_size * sizeof(float), 0);

    wcum_kernel<<<DIN, DOUT>>>(W);

    // s in blockIdx.x so consecutive blocks reuse the same X rows (L2-hot).
    dim3 g(NSUP, MTILES, 2);
    gemm_kernel<<<g, 128>>>(U, It);

    const int spmmBlocks = (NEDGE * 32 + 255) / 256;
    for (int s = 0; s < NSUP; s++)
        spmm_kernel<<<spmmBlocks, 256>>>(u_rows + (size_t)s * NEDGE,
                                         u_cols + (size_t)s * NEDGE,
                                         u_vals + (size_t)s * NEDGE,
                                         1, s, out, NEDGE);
    for (int s = 0; s < NSUP; s++)
        spmm_kernel<<<spmmBlocks, 256>>>(i_rows + (size_t)s * NEDGE,
                                         i_cols + (size_t)s * NEDGE,
                                         i_vals + (size_t)s * NEDGE,
                                         0, s, out + (size_t)NUSERS * 128, NEDGE);

    const int n4 = (NUSERS + NITEMS) * 128 / 4;
    relu_kernel<<<(n4 + 255) / 256, 256>>>(out, n4);
}

// round 3
// speedup vs baseline: 2.6474x; 2.4224x over previous
#include <cuda_runtime.h>
#include <cstdint>
#include <cstddef>

#define NUSERS 100000
#define NITEMS 100000
#define DIN 128
#define DOUT 128
#define NSUP 5
#define NEDGE 500000
#define MTILES ((NUSERS + 127) / 128)
#define NBINS (2 * NSUP * NUSERS)          // 1,000,000 bins (side,s,row)
#define NCHUNK ((NBINS + 1023) / 1024)     // 977
#define TOTE (2 * NSUP * NEDGE)            // 5,000,000 edges

// ---------------------------------------------------------------------------
// Device scratch
// ---------------------------------------------------------------------------
__device__ float g_Wc[NSUP][DIN * DOUT];              // tf32-rounded cumulative W
__device__ float g_G[2][NSUP][(size_t)NUSERS * 128];  // 512 MB: A_s @ inputs
__device__ int g_cnt[NBINS];                          // histogram, then cursor
__device__ int g_off[NBINS + 1];                      // CSR offsets
__device__ int g_blksum[1024];                        // scan block sums
__device__ int2 g_edges[TOTE];                        // {col, val_bits} binned

// ---------------------------------------------------------------------------
// Cumulative weight, rounded to tf32.  weight layout [din][dout][s]
// ---------------------------------------------------------------------------
__global__ void wcum_kernel(const float* __restrict__ w) {
    int din = blockIdx.x;
    int dout = threadIdx.x;
    const float* p = w + ((size_t)din * DOUT + dout) * NSUP;
    float acc = 0.f;
#pragma unroll
    for (int s = 0; s < NSUP; s++) {
        acc += p[s];
        uint32_t r;
        asm("cvt.rna.tf32.f32 %0, %1;" : "=r"(r) : "f"(acc));
        g_Wc[s][din * DOUT + dout] = __uint_as_float(r);
    }
}

// ---------------------------------------------------------------------------
// CSR build: zero -> histogram -> scan(3) -> scatter
// bin = (side*NSUP + s)*NUSERS + row
// ---------------------------------------------------------------------------
__global__ void zero_kernel() {
    int i = blockIdx.x * 256 + threadIdx.x;
    if (i < NBINS) g_cnt[i] = 0;
}

__global__ void hist_kernel(const int* __restrict__ rows, int sidebase) {
    int e = blockIdx.x * 256 + threadIdx.x;
    if (e >= NSUP * NEDGE) return;
    int s = e / NEDGE;
    int bin = (sidebase * NSUP + s) * NUSERS + __ldg(&rows[e]);
    atomicAdd(&g_cnt[bin], 1);
}

__global__ __launch_bounds__(256) void scan1_kernel() {
    __shared__ int s0[256], s1[256];
    int b = blockIdx.x, tid = threadIdx.x;
    int base = b * 1024 + tid * 4;
    int v[4];
#pragma unroll
    for (int j = 0; j < 4; j++) {
        int idx = base + j;
        v[j] = (idx < NBINS) ? g_cnt[idx] : 0;
    }
    int tsum = v[0] + v[1] + v[2] + v[3];
    s0[tid] = tsum;
    __syncthreads();
    int* src = s0;
    int* dst = s1;
#pragma unroll
    for (int o = 1; o < 256; o <<= 1) {
        int x = src[tid];
        if (tid >= o) x += src[tid - o];
        __syncthreads();
        dst[tid] = x;
        __syncthreads();
        int* tmp = src; src = dst; dst = tmp;
    }
    int run = (tid == 0) ? 0 : src[tid - 1];
#pragma unroll
    for (int j = 0; j < 4; j++) {
        int idx = base + j;
        if (idx < NBINS) g_off[idx] = run;
        run += v[j];
    }
    if (tid == 255) g_blksum[b] = src[255];
}

__global__ __launch_bounds__(1024) void scan2_kernel() {
    __shared__ int s0[1024], s1[1024];
    int tid = threadIdx.x;
    s0[tid] = (tid < NCHUNK) ? g_blksum[tid] : 0;
    __syncthreads();
    int* src = s0;
    int* dst = s1;
#pragma unroll
    for (int o = 1; o < 1024; o <<= 1) {
        int x = src[tid];
        if (tid >= o) x += src[tid - o];
        __syncthreads();
        dst[tid] = x;
        __syncthreads();
        int* tmp = src; src = dst; dst = tmp;
    }
    int excl = (tid == 0) ? 0 : src[tid - 1];
    if (tid < NCHUNK) g_blksum[tid] = excl;
    if (tid == 0) g_off[NBINS] = TOTE;
}

__global__ __launch_bounds__(256) void scan3_kernel() {
    int b = blockIdx.x;
    int add = g_blksum[b];
#pragma unroll
    for (int j = 0; j < 4; j++) {
        int idx = b * 1024 + threadIdx.x + 256 * j;
        if (idx < NBINS) {
            int o = g_off[idx] + add;
            g_off[idx] = o;
            g_cnt[idx] = o;  // cursor init
        }
    }
}

__global__ void scatter_kernel(const int* __restrict__ rows,
                               const int* __restrict__ cols,
                               const float* __restrict__ vals, int sidebase) {
    int e = blockIdx.x * 256 + threadIdx.x;
    if (e >= NSUP * NEDGE) return;
    int s = e / NEDGE;
    int bin = (sidebase * NSUP + s) * NUSERS + __ldg(&rows[e]);
    int pos = atomicAdd(&g_cnt[bin], 1);
    g_edges[pos] = make_int2(__ldg(&cols[e]), __float_as_int(__ldg(&vals[e])));
}

// ---------------------------------------------------------------------------
// Atomic-free gather SpMM: one warp per (side,row), loops over 5 supports.
// G[side][s][row] = sum_e val_e * inputs[col_e]
// side 0 (user dest) gathers from item_inputs; side 1 from user_inputs.
// ---------------------------------------------------------------------------
__global__ __launch_bounds__(256) void gather_kernel(const float* __restrict__ U,
                                                     const float* __restrict__ It) {
    int w = (int)((blockIdx.x * 256u + threadIdx.x) >> 5);
    if (w >= 2 * NUSERS) return;
    int lane = threadIdx.x & 31;
    int side = (w >= NUSERS) ? 1 : 0;
    int row = w - side * NUSERS;
    const float4* src = (const float4*)(side == 0 ? It : U);

#pragma unroll
    for (int s = 0; s < NSUP; s++) {
        int bin = (side * NSUP + s) * NUSERS + row;
        int e0 = g_off[bin];
        int e1 = g_off[bin + 1];
        float4 acc = make_float4(0.f, 0.f, 0.f, 0.f);
        for (int e = e0; e < e1; e++) {
            int2 p = g_edges[e];
            float v = __int_as_float(p.y);
            float4 x = src[(size_t)p.x * 32 + lane];
            acc.x += v * x.x;
            acc.y += v * x.y;
            acc.z += v * x.z;
            acc.w += v * x.w;
        }
        ((float4*)(g_G[side][s] + (size_t)row * 128))[lane] = acc;
    }
}

// ---------------------------------------------------------------------------
// Tensor GEMM, K = 640:  out[side] = relu( [G_0|...|G_4] @ [Wc_0;...;Wc_4] )
// Block 128 thr = 4 warps, tile 128x128, KC=16 double-buffered cp.async.
// ---------------------------------------------------------------------------
#define KC 16
#define ASTR 20
#define BSTR 136

__device__ __forceinline__ void cp16(float* sdst, const float* gsrc) {
    unsigned u = (unsigned)__cvta_generic_to_shared(sdst);
    asm volatile("cp.async.cg.shared.global [%0], [%1], 16;" :: "r"(u), "l"(gsrc));
}

#define MMA_TF32(c, a, b)                                                    \
    asm volatile(                                                            \
        "mma.sync.aligned.m16n8k8.row.col.f32.tf32.tf32.f32 "               \
        "{%0,%1,%2,%3}, {%4,%5,%6,%7}, {%8,%9}, {%0,%1,%2,%3};"             \
        : "+f"(c[0]), "+f"(c[1]), "+f"(c[2]), "+f"(c[3])                     \
        : "r"(a[0]), "r"(a[1]), "r"(a[2]), "r"(a[3]), "r"(b[0]), "r"(b[1]))

__global__ __launch_bounds__(128) void gemm_kernel(float* __restrict__ out) {
    const int side = blockIdx.y;
    const int row0 = blockIdx.x * 128;

    __shared__ float sA[2][128 * ASTR];
    __shared__ float sB[2][KC * BSTR];

    const int t = threadIdx.x;
    const int wid = t >> 5;
    const int lane = t & 31;
    const int gid = lane >> 2;
    const int tig = lane & 3;
    const int wm = (wid & 1) * 64;
    const int wn = (wid >> 1) * 64;

    float c[4][8][4];
#pragma unroll
    for (int mt = 0; mt < 4; mt++)
#pragma unroll
        for (int nt = 0; nt < 8; nt++)
#pragma unroll
            for (int i = 0; i < 4; i++) c[mt][nt][i] = 0.f;

    auto copy_chunk = [&](int kc, int b) {
        const float* Asrc = g_G[side][kc >> 3];
        const float* Bsrc = g_Wc[kc >> 3];
        const int kk0 = (kc & 7) * 16;
#pragma unroll
        for (int i = 0; i < 4; i++) {
            int q = t + 128 * i;
            int row = q >> 2, c4 = (q & 3) * 4;
            int gr = row0 + row;
            if (gr > NUSERS - 1) gr = NUSERS - 1;
            cp16(&sA[b][row * ASTR + c4], Asrc + (size_t)gr * 128 + kk0 + c4);
        }
#pragma unroll
        for (int i = 0; i < 4; i++) {
            int q = t + 128 * i;
            int kr = q >> 5, c4 = (q & 31) * 4;
            cp16(&sB[b][kr * BSTR + c4], Bsrc + (size_t)(kk0 + kr) * 128 + c4);
        }
        asm volatile("cp.async.commit_group;");
    };

    copy_chunk(0, 0);
    int buf = 0;

#pragma unroll 1
    for (int kc = 0; kc < 640 / KC; kc++) {
        if (kc + 1 < 640 / KC) {
            copy_chunk(kc + 1, buf ^ 1);
            asm volatile("cp.async.wait_group 1;");
        } else {
            asm volatile("cp.async.wait_group 0;");
        }
        __syncthreads();

        const float* A = sA[buf];
        const float* B = sB[buf];
#pragma unroll
        for (int ks = 0; ks < KC / 8; ks++) {
            uint32_t a[4][4], b[8][2];
#pragma unroll
            for (int mt = 0; mt < 4; mt++) {
                int r = wm + mt * 16 + gid;
                int kk = ks * 8 + tig;
                float f0 = A[r * ASTR + kk];
                float f1 = A[(r + 8) * ASTR + kk];
                float f2 = A[r * ASTR + kk + 4];
                float f3 = A[(r + 8) * ASTR + kk + 4];
                asm("cvt.rna.tf32.f32 %0, %1;" : "=r"(a[mt][0]) : "f"(f0));
                asm("cvt.rna.tf32.f32 %0, %1;" : "=r"(a[mt][1]) : "f"(f1));
                asm("cvt.rna.tf32.f32 %0, %1;" : "=r"(a[mt][2]) : "f"(f2));
                asm("cvt.rna.tf32.f32 %0, %1;" : "=r"(a[mt][3]) : "f"(f3));
            }
#pragma unroll
            for (int nt = 0; nt < 8; nt++) {
                int col = wn + nt * 8 + gid;
                b[nt][0] = __float_as_uint(B[(ks * 8 + tig) * BSTR + col]);
                b[nt][1] = __float_as_uint(B[(ks * 8 + tig + 4) * BSTR + col]);
            }
#pragma unroll
            for (int mt = 0; mt < 4; mt++)
#pragma unroll
                for (int nt = 0; nt < 8; nt++) MMA_TF32(c[mt][nt], a[mt], b[nt]);
        }
        buf ^= 1;
        __syncthreads();
    }

    float* O = out + (size_t)side * NUSERS * 128;
#pragma unroll
    for (int mt = 0; mt < 4; mt++) {
        int r0 = row0 + wm + mt * 16 + gid;
        int r1 = r0 + 8;
#pragma unroll
        for (int nt = 0; nt < 8; nt++) {
            int cg = wn + nt * 8 + tig * 2;
            if (r0 < NUSERS)
                *(float2*)&O[(size_t)r0 * 128 + cg] =
                    make_float2(fmaxf(c[mt][nt][0], 0.f), fmaxf(c[mt][nt][1], 0.f));
            if (r1 < NUSERS)
                *(float2*)&O[(size_t)r1 * 128 + cg] =
                    make_float2(fmaxf(c[mt][nt][2], 0.f), fmaxf(c[mt][nt][3], 0.f));
        }
    }
}

// ---------------------------------------------------------------------------
// kernel_launch
// ---------------------------------------------------------------------------
extern "C" void kernel_launch(void* const* d_in, const int* in_sizes, int n_in,
                              void* d_out, int out_size) {
    const float* U = (const float*)d_in[0];
    const float* It = (const float*)d_in[1];
    const float* W = (const float*)d_in[2];
    const int* u_rows = (const int*)d_in[3];
    const int* u_cols = (const int*)d_in[4];
    const float* u_vals = (const float*)d_in[5];
    const int* i_rows = (const int*)d_in[6];
    const int* i_cols = (const int*)d_in[7];
    const float* i_vals = (const float*)d_in[8];
    float* out = (float*)d_out;

    wcum_kernel<<<DIN, DOUT>>>(W);

    // --- CSR build ---
    zero_kernel<<<(NBINS + 255) / 256, 256>>>();
    const int eb = (NSUP * NEDGE + 255) / 256;
    hist_kernel<<<eb, 256>>>(u_rows, 0);
    hist_kernel<<<eb, 256>>>(i_rows, 1);
    scan1_kernel<<<NCHUNK, 256>>>();
    scan2_kernel<<<1, 1024>>>();
    scan3_kernel<<<NCHUNK, 256>>>();
    scatter_kernel<<<eb, 256>>>(u_rows, u_cols, u_vals, 0);
    scatter_kernel<<<eb, 256>>>(i_rows, i_cols, i_vals, 1);

    // --- atomic-free SpMM of raw inputs ---
    gather_kernel<<<(2 * NUSERS * 32 + 255) / 256, 256>>>(U, It);

    // --- K=640 GEMM + fused ReLU (writes the whole output; no memset) ---
    dim3 g(MTILES, 2);
    gemm_kernel<<<g, 128>>>(out);
}